// round 15
// baseline (speedup 1.0000x reference)
#include <cuda_runtime.h>
#include <cuda_fp16.h>
#include <math.h>

// Problem constants
#define B_  32
#define C_  273
#define CP_ 288    // padded channel dim
#define T_  3000
#define O_  270
#define D_  2048   // 2 * 32^2

// Scratch (allocation-free rule: __device__ globals)
__device__ __half g_emb[(size_t)B_ * C_ * D_];      // [B*C, 2048] fp16
__device__ float  g_scores[(size_t)B_ * O_ * CP_];  // raw scores fp32
__device__ __half g_wh[(size_t)B_ * O_ * CP_];      // softmax weights fp16, pads=0
__device__ __half g_headsh[(size_t)O_ * D_];        // heads fp16
__device__ __half g_brainh[(size_t)B_ * C_ * T_];   // brain fp16

// ---------------------------------------------------------------------------
// helpers
// ---------------------------------------------------------------------------
__device__ __forceinline__ void cp16(void* dst, const void* src, bool p) {
    unsigned d = (unsigned)__cvta_generic_to_shared(dst);
    int sz = p ? 16 : 0;
    asm volatile("cp.async.ca.shared.global [%0], [%1], 16, %2;" :: "r"(d), "l"(src), "r"(sz));
}
#define CP_COMMIT() asm volatile("cp.async.commit_group;")
#define CP_WAIT0()  asm volatile("cp.async.wait_group 0;")

__device__ __forceinline__ void mma16(float* c, const unsigned* a, const unsigned* b) {
    asm volatile("mma.sync.aligned.m16n8k16.row.col.f32.f16.f16.f32 "
        "{%0,%1,%2,%3},{%4,%5,%6,%7},{%8,%9},{%0,%1,%2,%3};"
        : "+f"(c[0]), "+f"(c[1]), "+f"(c[2]), "+f"(c[3])
        : "r"(a[0]), "r"(a[1]), "r"(a[2]), "r"(a[3]), "r"(b[0]), "r"(b[1]));
}

__device__ __forceinline__ void ldsm4(unsigned* r, const void* p) {
    unsigned a = (unsigned)__cvta_generic_to_shared(p);
    asm volatile("ldmatrix.sync.aligned.m8n8.x4.shared.b16 {%0,%1,%2,%3}, [%4];"
        : "=r"(r[0]), "=r"(r[1]), "=r"(r[2]), "=r"(r[3]) : "r"(a));
}
__device__ __forceinline__ void ldsm2(unsigned* r, const void* p) {
    unsigned a = (unsigned)__cvta_generic_to_shared(p);
    asm volatile("ldmatrix.sync.aligned.m8n8.x2.shared.b16 {%0,%1}, [%2];"
        : "=r"(r[0]), "=r"(r[1]) : "r"(a));
}
__device__ __forceinline__ void ldsm2t(unsigned* r, const void* p) {
    unsigned a = (unsigned)__cvta_generic_to_shared(p);
    asm volatile("ldmatrix.sync.aligned.m8n8.x2.trans.shared.b16 {%0,%1}, [%2];"
        : "=r"(r[0]), "=r"(r[1]) : "r"(a));
}

// ---------------------------------------------------------------------------
// Kernel 0a: heads -> fp16
// ---------------------------------------------------------------------------
__global__ __launch_bounds__(256) void heads_kernel(const float* __restrict__ heads) {
    int i = blockIdx.x * 256 + threadIdx.x;
    if (i < O_ * D_) g_headsh[i] = __float2half(heads[i]);
}

// ---------------------------------------------------------------------------
// Kernel 0b: brain -> fp16 (streaming, 8 elems/thread)
// ---------------------------------------------------------------------------
__global__ __launch_bounds__(256) void brain_kernel(const float* __restrict__ brain) {
    size_t i = ((size_t)blockIdx.x * 256 + threadIdx.x) * 8;
    if (i >= (size_t)B_ * C_ * T_) return;
    float4 a = *(const float4*)(brain + i);
    float4 b = *(const float4*)(brain + i + 4);
    __half2 h[4];
    h[0] = __floats2half2_rn(a.x, a.y);
    h[1] = __floats2half2_rn(a.z, a.w);
    h[2] = __floats2half2_rn(b.x, b.y);
    h[3] = __floats2half2_rn(b.z, b.w);
    *(uint4*)(g_brainh + i) = *(uint4*)h;
}

// ---------------------------------------------------------------------------
// Kernel 1: fourier embedding (angle addition), fp16 half2 output
// ---------------------------------------------------------------------------
__global__ __launch_bounds__(256) void emb_kernel(const float* __restrict__ layout) {
    __shared__ float sx[32], cx[32], sy[32], cy[32];
    int bc = blockIdx.x;
    float px = (layout[bc * 2 + 0] + 0.1f) / 1.2f;
    float py = (layout[bc * 2 + 1] + 0.1f) / 1.2f;
    if (threadIdx.x < 64) {
        int axis = threadIdx.x >> 5;
        int i = threadIdx.x & 31;
        float p = axis ? py : px;
        float t = p * (float)i;
        t -= floorf(t);
        float s, c;
        sincosf(6.28318530717958647692f * t, &s, &c);
        if (axis == 0) { sx[i] = s; cx[i] = c; }
        else           { sy[i] = s; cy[i] = c; }
    }
    __syncthreads();
    __half2* e = (__half2*)(g_emb + (size_t)bc * D_);
    for (int p2 = threadIdx.x; p2 < 512; p2 += 256) {
        int i = p2 >> 4, j = (p2 & 15) * 2;
        float si = sx[i], ci = cx[i];
        float s0 = sy[j], c0 = cy[j], s1 = sy[j + 1], c1 = cy[j + 1];
        e[p2]       = __floats2half2_rn(si * c0 + ci * s0, si * c1 + ci * s1);  // sin
        e[p2 + 512] = __floats2half2_rn(ci * c0 - si * s0, ci * c1 - si * s1);  // cos
    }
}

// ---------------------------------------------------------------------------
// Kernel 2: scores[b,o,c] = sum_d headsh[o,d] * emb[b,c,d]  (both fp16 k-major)
// mma.sync m16n8k16, CTA 96x96, 6 warps (3x2, warp 32x48), K-chunk 64,
// single sync per chunk.  (R14 config — measured 38.2us.)
// ---------------------------------------------------------------------------
#define SC_TILE (2 * 96 * 72)            // halves per array
#define SC_SMEM (2 * SC_TILE * 2)        // 55296 bytes

__global__ __launch_bounds__(192) void scores_kernel() {
    extern __shared__ __half sc_smem[];
    __half* As = sc_smem;                // [2][96][72]
    __half* Bs = sc_smem + SC_TILE;      // [2][96][72]
    int b  = blockIdx.z;
    int m0 = blockIdx.y * 96;
    int n0 = blockIdx.x * 96;
    const __half* E = g_emb + (size_t)b * C_ * D_;
    int t = threadIdx.x;
    int w = t >> 5, lane = t & 31;
    int wm = (w >> 1) * 32, wn = (w & 1) * 48;
    int g = lane >> 2, q4 = lane & 3;
    int l15 = lane & 15, lhi = (lane >> 4) << 3;
    int l7 = lane & 7,  lk8 = ((lane >> 3) & 1) << 3;

    float acc[2][6][4] = {};

    auto load = [&](int kb, int s) {
        int k0 = kb * 64;
#pragma unroll
        for (int q = 0; q < 4; q++) {    // 96 rows x 64 halves = 768 cp16 per array
            int idx = t + 192 * q;
            int r = idx >> 3, c8 = (idx & 7) * 8;
            bool pa = (m0 + r) < O_;
            cp16(As + ((size_t)s * 96 + r) * 72 + c8,
                 g_headsh + (size_t)(pa ? m0 + r : 0) * D_ + k0 + c8, pa);
            bool pb = (n0 + r) < C_;
            cp16(Bs + ((size_t)s * 96 + r) * 72 + c8,
                 E + (size_t)(pb ? n0 + r : 0) * D_ + k0 + c8, pb);
        }
        CP_COMMIT();
    };

    load(0, 0);
    const int KB = D_ / 64;   // 32
    for (int kb = 0; kb < KB; kb++) {
        int s = kb & 1;
        CP_WAIT0();
        __syncthreads();
        if (kb + 1 < KB) load(kb + 1, s ^ 1);
#pragma unroll
        for (int k16 = 0; k16 < 4; k16++) {
            int kk = k16 * 16;
            unsigned a[2][4], bf[6][2];
#pragma unroll
            for (int i = 0; i < 2; i++)
                ldsm4(a[i], As + ((size_t)s * 96 + wm + i * 16 + l15) * 72 + kk + lhi);
#pragma unroll
            for (int j = 0; j < 6; j++)
                ldsm2(bf[j], Bs + ((size_t)s * 96 + wn + j * 8 + l7) * 72 + kk + lk8);
#pragma unroll
            for (int i = 0; i < 2; i++)
#pragma unroll
                for (int j = 0; j < 6; j++) mma16(acc[i][j], a[i], bf[j]);
        }
    }

    float* S = g_scores + (size_t)b * O_ * CP_;
#pragma unroll
    for (int i = 0; i < 2; i++)
#pragma unroll
        for (int j = 0; j < 6; j++) {
            int m = m0 + wm + i * 16 + g;
            int n = n0 + wn + j * 8 + 2 * q4;
            if (n < CP_) {
                if (m < O_)
                    *(float2*)(S + (size_t)m * CP_ + n) = make_float2(acc[i][j][0], acc[i][j][1]);
                if (m + 8 < O_)
                    *(float2*)(S + (size_t)(m + 8) * CP_ + n) = make_float2(acc[i][j][2], acc[i][j][3]);
            }
        }
}

// ---------------------------------------------------------------------------
// Kernel 3: softmax over channels (273 real), writes fp16 weights, pads -> 0
// ---------------------------------------------------------------------------
__global__ __launch_bounds__(256) void softmax_kernel() {
    int warp = (blockIdx.x * blockDim.x + threadIdx.x) >> 5;
    int lane = threadIdx.x & 31;
    if (warp >= B_ * O_) return;
    const float* row = g_scores + (size_t)warp * CP_;
    __half* roww = g_wh + (size_t)warp * CP_;

    float v[9];
    float m = -INFINITY;
#pragma unroll
    for (int i = 0; i < 9; i++) {
        int c = lane + i * 32;
        v[i] = (c < C_) ? row[c] : -INFINITY;
        m = fmaxf(m, v[i]);
    }
#pragma unroll
    for (int o = 16; o; o >>= 1) m = fmaxf(m, __shfl_xor_sync(0xffffffffu, m, o));
    float s = 0.f;
#pragma unroll
    for (int i = 0; i < 9; i++) {
        int c = lane + i * 32;
        if (c < C_) { v[i] = expf(v[i] - m); s += v[i]; }
    }
#pragma unroll
    for (int o = 16; o; o >>= 1) s += __shfl_xor_sync(0xffffffffu, s, o);
    float inv = 1.f / s;
#pragma unroll
    for (int i = 0; i < 9; i++) {
        int c = lane + i * 32;
        roww[c] = (c < C_) ? __float2half(v[i] * inv) : __float2half(0.f);
    }
}

// ---------------------------------------------------------------------------
// Kernel 4: out[b,o,t] = sum_c W[b,o,c] * brainh[b,c,t]  (all fp16 operands)
// CTA 96m x 128n, 6 warps (3m x 2n, warp-tile 32x64), K-chunk 32,
// single sync per chunk (wait -> sync -> issue next -> compute).
// ---------------------------------------------------------------------------
__global__ __launch_bounds__(192) void out_kernel(float* __restrict__ out) {
    __shared__ __half As[2][96][40];    // [m][k32], stride 40h
    __shared__ __half Bs[2][32][136];   // [k32][n128], stride 136h (trans-LDSM clean)
    int b  = blockIdx.z;
    int m0 = blockIdx.y * 96;
    int n0 = blockIdx.x * 128;
    const __half* W = g_wh + (size_t)b * O_ * CP_;
    const __half* X = g_brainh + (size_t)b * C_ * T_;
    int t = threadIdx.x;
    int w = t >> 5, lane = t & 31;
    int wm = (w >> 1) * 32;          // 0,32,64
    int wn = (w & 1) * 64;           // 0,64
    int g = lane >> 2, q4 = lane & 3;
    int l15 = lane & 15, lhi = (lane >> 4) << 3;
    int bkrow = (lane & 7) + (((lane >> 3) & 1) << 3);   // trans-B k row

    float acc[2][8][4] = {};         // [mi(16)][nj(8)][4] = 64 regs

    auto load = [&](int kb, int s) {
        int k0 = kb * 32;
#pragma unroll
        for (int q = 0; q < 2; q++) {   // A: 96 rows x 32 halves = 384 cp16
            int idx = t + 192 * q;
            int r = idx >> 2, c8 = (idx & 3) * 8;
            bool pa = (m0 + r) < O_;
            cp16(&As[s][r][c8], W + (size_t)(pa ? m0 + r : 0) * CP_ + k0 + c8, pa);
        }
#pragma unroll
        for (int q = 0; q < 3; q++) {   // B: 32 rows x 128 halves = 512 cp16
            int idx = t + 192 * q;
            if (idx < 512) {
                int r = idx >> 4, c8 = (idx & 15) * 8;
                int kk = k0 + r, n = n0 + c8;
                bool pb = (kk < C_) && (n < T_);
                cp16(&Bs[s][r][c8], X + (size_t)(pb ? kk : 0) * T_ + (pb ? n : 0), pb);
            }
        }
        CP_COMMIT();
    };

    load(0, 0);
    const int KB = CP_ / 32;   // 9
    for (int kb = 0; kb < KB; kb++) {
        int s = kb & 1;
        CP_WAIT0();
        __syncthreads();
        if (kb + 1 < KB) load(kb + 1, s ^ 1);
#pragma unroll
        for (int k16 = 0; k16 < 2; k16++) {
            int kk = k16 * 16;
            unsigned a[2][4], bf[8][2];
#pragma unroll
            for (int i = 0; i < 2; i++)
                ldsm4(a[i], &As[s][wm + i * 16 + l15][kk + lhi]);
#pragma unroll
            for (int j = 0; j < 8; j++)
                ldsm2t(bf[j], &Bs[s][kk + bkrow][wn + j * 8]);
#pragma unroll
            for (int i = 0; i < 2; i++)
#pragma unroll
                for (int j = 0; j < 8; j++) mma16(acc[i][j], a[i], bf[j]);
        }
    }

    float* Ob = out + (size_t)b * O_ * T_;
#pragma unroll
    for (int i = 0; i < 2; i++)
#pragma unroll
        for (int j = 0; j < 8; j++) {
            int m = m0 + wm + i * 16 + g;
            int n = n0 + wn + j * 8 + 2 * q4;
            if (n < T_) {
                if (m < O_)
                    *(float2*)(Ob + (size_t)m * T_ + n) = make_float2(acc[i][j][0], acc[i][j][1]);
                if (m + 8 < O_)
                    *(float2*)(Ob + (size_t)(m + 8) * T_ + n) = make_float2(acc[i][j][2], acc[i][j][3]);
            }
        }
}

// ---------------------------------------------------------------------------
extern "C" void kernel_launch(void* const* d_in, const int* in_sizes, int n_in,
                              void* d_out, int out_size) {
    const float* brain  = (const float*)d_in[0];  // [32, 273, 3000]
    const float* layout = (const float*)d_in[1];  // [32, 273, 2]
    const float* heads  = (const float*)d_in[2];  // [270, 2048]
    float* out = (float*)d_out;                   // [32, 270, 3000]

    cudaFuncSetAttribute(scores_kernel, cudaFuncAttributeMaxDynamicSharedMemorySize, SC_SMEM);

    heads_kernel<<<(O_ * D_ + 255) / 256, 256>>>(heads);
    brain_kernel<<<(B_ * C_ * T_ / 8 + 255) / 256, 256>>>(brain);
    emb_kernel<<<B_ * C_, 256>>>(layout);
    scores_kernel<<<dim3(3, 3, B_), 192, SC_SMEM>>>();      // 96x96 tiles, K-chunk 64
    softmax_kernel<<<(B_ * O_ * 32 + 255) / 256, 256>>>();
    out_kernel<<<dim3(24, 3, B_), 192>>>(out);              // 128n x 96m tiles
}

// round 16
// speedup vs baseline: 1.0727x; 1.0727x over previous
#include <cuda_runtime.h>
#include <cuda_fp16.h>
#include <math.h>

// Problem constants
#define B_  32
#define C_  273
#define CP_ 288    // padded channel dim
#define T_  3000
#define O_  270
#define D_  2048   // 2 * 32^2

// Scratch (allocation-free rule: __device__ globals)
__device__ __half g_emb[(size_t)B_ * C_ * D_];      // [B*C, 2048] fp16
__device__ float  g_scores[(size_t)B_ * O_ * CP_];  // raw scores fp32
__device__ __half g_wh[(size_t)B_ * O_ * CP_];      // softmax weights fp16, pads=0
__device__ __half g_headsh[(size_t)O_ * D_];        // heads fp16
__device__ __half g_brainh[(size_t)B_ * C_ * T_];   // brain fp16

// ---------------------------------------------------------------------------
// helpers
// ---------------------------------------------------------------------------
__device__ __forceinline__ void cp16(void* dst, const void* src, bool p) {
    unsigned d = (unsigned)__cvta_generic_to_shared(dst);
    int sz = p ? 16 : 0;
    asm volatile("cp.async.ca.shared.global [%0], [%1], 16, %2;" :: "r"(d), "l"(src), "r"(sz));
}
#define CP_COMMIT() asm volatile("cp.async.commit_group;")
#define CP_WAIT1()  asm volatile("cp.async.wait_group 1;")
#define CP_WAIT0()  asm volatile("cp.async.wait_group 0;")

__device__ __forceinline__ void mma16(float* c, const unsigned* a, const unsigned* b) {
    asm volatile("mma.sync.aligned.m16n8k16.row.col.f32.f16.f16.f32 "
        "{%0,%1,%2,%3},{%4,%5,%6,%7},{%8,%9},{%0,%1,%2,%3};"
        : "+f"(c[0]), "+f"(c[1]), "+f"(c[2]), "+f"(c[3])
        : "r"(a[0]), "r"(a[1]), "r"(a[2]), "r"(a[3]), "r"(b[0]), "r"(b[1]));
}

__device__ __forceinline__ void ldsm4(unsigned* r, const void* p) {
    unsigned a = (unsigned)__cvta_generic_to_shared(p);
    asm volatile("ldmatrix.sync.aligned.m8n8.x4.shared.b16 {%0,%1,%2,%3}, [%4];"
        : "=r"(r[0]), "=r"(r[1]), "=r"(r[2]), "=r"(r[3]) : "r"(a));
}
__device__ __forceinline__ void ldsm2(unsigned* r, const void* p) {
    unsigned a = (unsigned)__cvta_generic_to_shared(p);
    asm volatile("ldmatrix.sync.aligned.m8n8.x2.shared.b16 {%0,%1}, [%2];"
        : "=r"(r[0]), "=r"(r[1]) : "r"(a));
}
__device__ __forceinline__ void ldsm2t(unsigned* r, const void* p) {
    unsigned a = (unsigned)__cvta_generic_to_shared(p);
    asm volatile("ldmatrix.sync.aligned.m8n8.x2.trans.shared.b16 {%0,%1}, [%2];"
        : "=r"(r[0]), "=r"(r[1]) : "r"(a));
}

// ---------------------------------------------------------------------------
// Kernel 0a: heads -> fp16
// ---------------------------------------------------------------------------
__global__ __launch_bounds__(256) void heads_kernel(const float* __restrict__ heads) {
    int i = blockIdx.x * 256 + threadIdx.x;
    if (i < O_ * D_) g_headsh[i] = __float2half(heads[i]);
}

// ---------------------------------------------------------------------------
// Kernel 0b: brain -> fp16 (streaming, 8 elems/thread)
// ---------------------------------------------------------------------------
__global__ __launch_bounds__(256) void brain_kernel(const float* __restrict__ brain) {
    size_t i = ((size_t)blockIdx.x * 256 + threadIdx.x) * 8;
    if (i >= (size_t)B_ * C_ * T_) return;
    float4 a = *(const float4*)(brain + i);
    float4 b = *(const float4*)(brain + i + 4);
    __half2 h[4];
    h[0] = __floats2half2_rn(a.x, a.y);
    h[1] = __floats2half2_rn(a.z, a.w);
    h[2] = __floats2half2_rn(b.x, b.y);
    h[3] = __floats2half2_rn(b.z, b.w);
    *(uint4*)(g_brainh + i) = *(uint4*)h;
}

// ---------------------------------------------------------------------------
// Kernel 1: fourier embedding (angle addition), fp16 half2 output
// ---------------------------------------------------------------------------
__global__ __launch_bounds__(256) void emb_kernel(const float* __restrict__ layout) {
    __shared__ float sx[32], cx[32], sy[32], cy[32];
    int bc = blockIdx.x;
    float px = (layout[bc * 2 + 0] + 0.1f) / 1.2f;
    float py = (layout[bc * 2 + 1] + 0.1f) / 1.2f;
    if (threadIdx.x < 64) {
        int axis = threadIdx.x >> 5;
        int i = threadIdx.x & 31;
        float p = axis ? py : px;
        float t = p * (float)i;
        t -= floorf(t);
        float s, c;
        sincosf(6.28318530717958647692f * t, &s, &c);
        if (axis == 0) { sx[i] = s; cx[i] = c; }
        else           { sy[i] = s; cy[i] = c; }
    }
    __syncthreads();
    __half2* e = (__half2*)(g_emb + (size_t)bc * D_);
    for (int p2 = threadIdx.x; p2 < 512; p2 += 256) {
        int i = p2 >> 4, j = (p2 & 15) * 2;
        float si = sx[i], ci = cx[i];
        float s0 = sy[j], c0 = cy[j], s1 = sy[j + 1], c1 = cy[j + 1];
        e[p2]       = __floats2half2_rn(si * c0 + ci * s0, si * c1 + ci * s1);  // sin
        e[p2 + 512] = __floats2half2_rn(ci * c0 - si * s0, ci * c1 - si * s1);  // cos
    }
}

// ---------------------------------------------------------------------------
// Kernel 2: scores[b,o,c] = sum_d headsh[o,d] * emb[b,c,d]  (both fp16 k-major)
// mma.sync m16n8k16, CTA 96x96, 6 warps (3x2, warp 32x48), K-chunk 64,
// single sync per chunk.  (R14 config — measured 38.1us.)
// ---------------------------------------------------------------------------
#define SC_TILE (2 * 96 * 72)            // halves per array
#define SC_SMEM (2 * SC_TILE * 2)        // 55296 bytes

__global__ __launch_bounds__(192) void scores_kernel() {
    extern __shared__ __half sc_smem[];
    __half* As = sc_smem;                // [2][96][72]
    __half* Bs = sc_smem + SC_TILE;      // [2][96][72]
    int b  = blockIdx.z;
    int m0 = blockIdx.y * 96;
    int n0 = blockIdx.x * 96;
    const __half* E = g_emb + (size_t)b * C_ * D_;
    int t = threadIdx.x;
    int w = t >> 5, lane = t & 31;
    int wm = (w >> 1) * 32, wn = (w & 1) * 48;
    int g = lane >> 2, q4 = lane & 3;
    int l15 = lane & 15, lhi = (lane >> 4) << 3;
    int l7 = lane & 7,  lk8 = ((lane >> 3) & 1) << 3;

    float acc[2][6][4] = {};

    auto load = [&](int kb, int s) {
        int k0 = kb * 64;
#pragma unroll
        for (int q = 0; q < 4; q++) {    // 96 rows x 64 halves = 768 cp16 per array
            int idx = t + 192 * q;
            int r = idx >> 3, c8 = (idx & 7) * 8;
            bool pa = (m0 + r) < O_;
            cp16(As + ((size_t)s * 96 + r) * 72 + c8,
                 g_headsh + (size_t)(pa ? m0 + r : 0) * D_ + k0 + c8, pa);
            bool pb = (n0 + r) < C_;
            cp16(Bs + ((size_t)s * 96 + r) * 72 + c8,
                 E + (size_t)(pb ? n0 + r : 0) * D_ + k0 + c8, pb);
        }
        CP_COMMIT();
    };

    load(0, 0);
    const int KB = D_ / 64;   // 32
    for (int kb = 0; kb < KB; kb++) {
        int s = kb & 1;
        CP_WAIT0();
        __syncthreads();
        if (kb + 1 < KB) load(kb + 1, s ^ 1);
#pragma unroll
        for (int k16 = 0; k16 < 4; k16++) {
            int kk = k16 * 16;
            unsigned a[2][4], bf[6][2];
#pragma unroll
            for (int i = 0; i < 2; i++)
                ldsm4(a[i], As + ((size_t)s * 96 + wm + i * 16 + l15) * 72 + kk + lhi);
#pragma unroll
            for (int j = 0; j < 6; j++)
                ldsm2(bf[j], Bs + ((size_t)s * 96 + wn + j * 8 + l7) * 72 + kk + lk8);
#pragma unroll
            for (int i = 0; i < 2; i++)
#pragma unroll
                for (int j = 0; j < 6; j++) mma16(acc[i][j], a[i], bf[j]);
        }
    }

    float* S = g_scores + (size_t)b * O_ * CP_;
#pragma unroll
    for (int i = 0; i < 2; i++)
#pragma unroll
        for (int j = 0; j < 6; j++) {
            int m = m0 + wm + i * 16 + g;
            int n = n0 + wn + j * 8 + 2 * q4;
            if (n < CP_) {
                if (m < O_)
                    *(float2*)(S + (size_t)m * CP_ + n) = make_float2(acc[i][j][0], acc[i][j][1]);
                if (m + 8 < O_)
                    *(float2*)(S + (size_t)(m + 8) * CP_ + n) = make_float2(acc[i][j][2], acc[i][j][3]);
            }
        }
}

// ---------------------------------------------------------------------------
// Kernel 3: softmax over channels (273 real), writes fp16 weights, pads -> 0
// ---------------------------------------------------------------------------
__global__ __launch_bounds__(256) void softmax_kernel() {
    int warp = (blockIdx.x * blockDim.x + threadIdx.x) >> 5;
    int lane = threadIdx.x & 31;
    if (warp >= B_ * O_) return;
    const float* row = g_scores + (size_t)warp * CP_;
    __half* roww = g_wh + (size_t)warp * CP_;

    float v[9];
    float m = -INFINITY;
#pragma unroll
    for (int i = 0; i < 9; i++) {
        int c = lane + i * 32;
        v[i] = (c < C_) ? row[c] : -INFINITY;
        m = fmaxf(m, v[i]);
    }
#pragma unroll
    for (int o = 16; o; o >>= 1) m = fmaxf(m, __shfl_xor_sync(0xffffffffu, m, o));
    float s = 0.f;
#pragma unroll
    for (int i = 0; i < 9; i++) {
        int c = lane + i * 32;
        if (c < C_) { v[i] = expf(v[i] - m); s += v[i]; }
    }
#pragma unroll
    for (int o = 16; o; o >>= 1) s += __shfl_xor_sync(0xffffffffu, s, o);
    float inv = 1.f / s;
#pragma unroll
    for (int i = 0; i < 9; i++) {
        int c = lane + i * 32;
        roww[c] = (c < C_) ? __float2half(v[i] * inv) : __float2half(0.f);
    }
}

// ---------------------------------------------------------------------------
// Kernel 4: out[b,o,t] = sum_c W[b,o,c] * brainh[b,c,t]  (all fp16 operands)
// mma.sync m16n8k16, CTA 64x128, 4 warps (warp-tile 64x32), K-chunk 32,
// 2-stage pipeline with load-before-wait (R7 config — inside the 149.5us run).
// ---------------------------------------------------------------------------
__global__ __launch_bounds__(128) void out_kernel(float* __restrict__ out) {
    __shared__ __half As[2][64][40];
    __shared__ __half Bs[2][32][136];
    int b  = blockIdx.z;
    int m0 = blockIdx.y * 64;
    int n0 = blockIdx.x * 128;
    const __half* W = g_wh + (size_t)b * O_ * CP_;
    const __half* X = g_brainh + (size_t)b * C_ * T_;
    int t = threadIdx.x;
    int w = t >> 5, lane = t & 31;
    int wn = w * 32;
    int g = lane >> 2, q4 = lane & 3;
    int l15 = lane & 15, lhi = (lane >> 4) << 3;
    int bkrow = (lane & 7) + (((lane >> 3) & 1) << 3);

    float acc[4][4][4] = {};

    auto load = [&](int kb, int s) {
        int k0 = kb * 32;
#pragma unroll
        for (int q = 0; q < 2; q++) {
            int idx = t + 128 * q;
            int r = idx >> 2, c8 = (idx & 3) * 8;
            bool pa = (m0 + r) < O_;
            cp16(&As[s][r][c8], W + (size_t)(pa ? m0 + r : 0) * CP_ + k0 + c8, pa);
        }
#pragma unroll
        for (int q = 0; q < 4; q++) {
            int idx = t + 128 * q;
            int r = idx >> 4, c8 = (idx & 15) * 8;
            int kk = k0 + r, n = n0 + c8;
            bool pb = (kk < C_) && (n < T_);
            cp16(&Bs[s][r][c8], X + (size_t)(pb ? kk : 0) * T_ + (pb ? n : 0), pb);
        }
        CP_COMMIT();
    };

    load(0, 0);
    const int KB = CP_ / 32;   // 9
    for (int kb = 0; kb < KB; kb++) {
        int s = kb & 1;
        if (kb + 1 < KB) { load(kb + 1, s ^ 1); CP_WAIT1(); }
        else CP_WAIT0();
        __syncthreads();
#pragma unroll
        for (int k16 = 0; k16 < 2; k16++) {
            int kk = k16 * 16;
            unsigned a[4][4], bf[4][2];
#pragma unroll
            for (int i = 0; i < 4; i++)
                ldsm4(a[i], &As[s][i * 16 + l15][kk + lhi]);
#pragma unroll
            for (int j = 0; j < 4; j++)
                ldsm2t(bf[j], &Bs[s][kk + bkrow][wn + j * 8]);
#pragma unroll
            for (int i = 0; i < 4; i++)
#pragma unroll
                for (int j = 0; j < 4; j++) mma16(acc[i][j], a[i], bf[j]);
        }
        __syncthreads();
    }

    float* Ob = out + (size_t)b * O_ * T_;
#pragma unroll
    for (int i = 0; i < 4; i++)
#pragma unroll
        for (int j = 0; j < 4; j++) {
            int m = m0 + i * 16 + g;
            int n = n0 + wn + j * 8 + 2 * q4;
            if (n < T_) {
                if (m < O_)
                    *(float2*)(Ob + (size_t)m * T_ + n) = make_float2(acc[i][j][0], acc[i][j][1]);
                if (m + 8 < O_)
                    *(float2*)(Ob + (size_t)(m + 8) * T_ + n) = make_float2(acc[i][j][2], acc[i][j][3]);
            }
        }
}

// ---------------------------------------------------------------------------
extern "C" void kernel_launch(void* const* d_in, const int* in_sizes, int n_in,
                              void* d_out, int out_size) {
    const float* brain  = (const float*)d_in[0];  // [32, 273, 3000]
    const float* layout = (const float*)d_in[1];  // [32, 273, 2]
    const float* heads  = (const float*)d_in[2];  // [270, 2048]
    float* out = (float*)d_out;                   // [32, 270, 3000]

    cudaFuncSetAttribute(scores_kernel, cudaFuncAttributeMaxDynamicSharedMemorySize, SC_SMEM);

    heads_kernel<<<(O_ * D_ + 255) / 256, 256>>>(heads);
    brain_kernel<<<(B_ * C_ * T_ / 8 + 255) / 256, 256>>>(brain);
    emb_kernel<<<B_ * C_, 256>>>(layout);
    scores_kernel<<<dim3(3, 3, B_), 192, SC_SMEM>>>();      // 96x96 tiles, K-chunk 64
    softmax_kernel<<<(B_ * O_ * 32 + 255) / 256, 256>>>();
    out_kernel<<<dim3(24, 5, B_), 128>>>(out);              // 128n x 64m tiles (R7)
}